// round 13
// baseline (speedup 1.0000x reference)
#include <cuda_runtime.h>
#include <cuda_fp16.h>
#include <cstdint>

#define HDIM 64
#define BN_EPS 1e-5f
#define MAXN 131072
#define MAXL 4

// Scratch (device globals — no allocation allowed). 16B-aligned.
__device__ __align__(16) __half g_y16[MAXN * HDIM]; // y = h @ Wa (fp16 gather)
__device__ __align__(16) float g_z[MAXN * HDIM];    // z = (1+eps)*y + scatter
__device__ __align__(16) float g_h2[MAXN * HDIM];   // pre-BN output of MLP
__device__ __align__(16) float g_h[MAXN * HDIM];    // residual stream
__device__ __align__(16) float g_sum[MAXL][HDIM];   // per-layer BN stats
__device__ __align__(16) float g_sumsq[MAXL][HDIM];

// tf32 helpers
#define TF32(u, f) asm("cvt.rna.tf32.f32 %0, %1;" : "=r"(u) : "f"(f))
#define MMA_TF32(d, a0, a1, a2, a3, b0, b1) \
    asm volatile("mma.sync.aligned.m16n8k8.row.col.f32.tf32.tf32.f32 " \
        "{%0,%1,%2,%3}, {%4,%5,%6,%7}, {%8,%9}, {%0,%1,%2,%3};" \
        : "+f"(d[0]), "+f"(d[1]), "+f"(d[2]), "+f"(d[3]) \
        : "r"(a0), "r"(a1), "r"(a2), "r"(a3), "r"(b0), "r"(b1))

#define WPAD 72   // Ws row stride in floats (conflict-free B-frag loads)

// ===========================================================================
// GEMM A: BM=128, 256 thr (8 warps 4x2), tf32 mma m16n8k8, fp32 accum.
// y16 = A' @ W (fp16 out for gather), z = (1+eps)*(A' @ W) (fp32).
// FUSE: A' = [residual +] relu(BN(h2)) on the fly, written to hbuf (fp32).
// AsT staged k-major with tf32-rounded values. BK=32 (K=64) / 16 (K=128).
// ===========================================================================
template <int K, bool FUSE>
__global__ __launch_bounds__(256) void gemm_a_kernel(
    const float* __restrict__ A, const float* __restrict__ W,
    const float* __restrict__ eps_ptr, int eps_idx,
    const float* __restrict__ gamma, const float* __restrict__ beta,
    int stat_set, int residual, float invN, int zero_stats,
    float* __restrict__ hbuf, __half* __restrict__ y16,
    float* __restrict__ z, int N)
{
    constexpr int BM = 128;
    constexpr int BK = (K == 64) ? 32 : 16;
    __shared__ __align__(16) float Ws[K][WPAD];
    __shared__ __align__(16) float AsT[BK][BM + 4];
    __shared__ __align__(16) float s_scale[HDIM], s_shift[HDIM];

    const int tid = threadIdx.x;
    const int lane = tid & 31, wid = tid >> 5;
    const int g = lane >> 2, tig = lane & 3;
    const int warpM = wid & 3, warpN = wid >> 2;
    const int r0 = blockIdx.x * BM;

    if (FUSE && tid < HDIM) {
        float mean = g_sum[stat_set][tid] * invN;
        float var  = g_sumsq[stat_set][tid] * invN - mean * mean;
        float sc   = gamma[tid] * rsqrtf(var + BN_EPS);
        s_scale[tid] = sc;
        s_shift[tid] = beta[tid] - mean * sc;
    }
    if (zero_stats && blockIdx.x == 0 && tid < HDIM) {
        #pragma unroll
        for (int s = 0; s < MAXL; s++) { g_sum[s][tid] = 0.f; g_sumsq[s][tid] = 0.f; }
    }

    {   // stage W, tf32-rounded, padded rows
        #pragma unroll
        for (int i = tid; i < K * 16; i += 256) {
            int row = i >> 4, c4 = (i & 15) * 4;
            float4 v = *(const float4*)(W + (size_t)row * HDIM + c4);
            uint32_t u0, u1, u2, u3;
            TF32(u0, v.x); TF32(u1, v.y); TF32(u2, v.z); TF32(u3, v.w);
            float4 o = make_float4(__uint_as_float(u0), __uint_as_float(u1),
                                   __uint_as_float(u2), __uint_as_float(u3));
            *(float4*)&Ws[row][c4] = o;
        }
    }

    float acc[2][4][4];
    #pragma unroll
    for (int m = 0; m < 2; m++)
        #pragma unroll
        for (int j = 0; j < 4; j++)
            #pragma unroll
            for (int q = 0; q < 4; q++) acc[m][j][q] = 0.f;

    constexpr int LPI = BK / 8;
    constexpr int RG  = BK / 4;
    for (int kk = 0; kk < K; kk += BK) {
        __syncthreads();                 // covers s_scale/Ws init on first trip
        #pragma unroll
        for (int pp = 0; pp < LPI; pp++) {
            int row = (tid / RG) + pp * (256 / RG);
            int c4 = (tid % RG) * 4;
            int gr = r0 + row;
            float4 v = make_float4(0.f, 0.f, 0.f, 0.f);
            if (gr < N) {
                v = *(const float4*)(A + (size_t)gr * K + kk + c4);
                if (FUSE) {
                    float4 sc = *(const float4*)&s_scale[kk + c4];
                    float4 sh = *(const float4*)&s_shift[kk + c4];
                    v.x = fmaxf(fmaf(v.x, sc.x, sh.x), 0.f);
                    v.y = fmaxf(fmaf(v.y, sc.y, sh.y), 0.f);
                    v.z = fmaxf(fmaf(v.z, sc.z, sh.z), 0.f);
                    v.w = fmaxf(fmaf(v.w, sc.w, sh.w), 0.f);
                    float* hp = hbuf + (size_t)gr * K + kk + c4;
                    if (residual) {
                        float4 h = *(const float4*)hp;
                        v.x += h.x; v.y += h.y; v.z += h.z; v.w += h.w;
                    }
                    *(float4*)hp = v;    // full fp32 residual stream
                }
            }
            uint32_t u0, u1, u2, u3;
            TF32(u0, v.x); TF32(u1, v.y); TF32(u2, v.z); TF32(u3, v.w);
            AsT[c4 + 0][row] = __uint_as_float(u0);
            AsT[c4 + 1][row] = __uint_as_float(u1);
            AsT[c4 + 2][row] = __uint_as_float(u2);
            AsT[c4 + 3][row] = __uint_as_float(u3);
        }
        __syncthreads();
        #pragma unroll
        for (int kc = 0; kc < BK / 8; kc++) {
            const int kl = kc * 8;
            uint32_t bf[4][2];
            #pragma unroll
            for (int j = 0; j < 4; j++) {
                int n = warpN * 32 + j * 8 + g;
                bf[j][0] = __float_as_uint(Ws[kk + kl + tig][n]);
                bf[j][1] = __float_as_uint(Ws[kk + kl + tig + 4][n]);
            }
            #pragma unroll
            for (int m = 0; m < 2; m++) {
                int rb = warpM * 32 + m * 16;
                uint32_t a0 = __float_as_uint(AsT[kl + tig][rb + g]);
                uint32_t a1 = __float_as_uint(AsT[kl + tig][rb + g + 8]);
                uint32_t a2 = __float_as_uint(AsT[kl + tig + 4][rb + g]);
                uint32_t a3 = __float_as_uint(AsT[kl + tig + 4][rb + g + 8]);
                #pragma unroll
                for (int j = 0; j < 4; j++)
                    MMA_TF32(acc[m][j], a0, a1, a2, a3, bf[j][0], bf[j][1]);
            }
        }
    }

    const float ep = 1.0f + eps_ptr[eps_idx];
    #pragma unroll
    for (int m = 0; m < 2; m++) {
        #pragma unroll
        for (int half = 0; half < 2; half++) {
            int gr = r0 + warpM * 32 + m * 16 + g + half * 8;
            if (gr < N) {
                #pragma unroll
                for (int j = 0; j < 4; j++) {
                    int col = warpN * 32 + j * 8 + 2 * tig;
                    float v0 = acc[m][j][half * 2 + 0];
                    float v1 = acc[m][j][half * 2 + 1];
                    *(float2*)(z + (size_t)gr * HDIM + col) =
                        make_float2(v0 * ep, v1 * ep);
                    *(__half2*)(y16 + (size_t)gr * HDIM + col) =
                        __float22half2_rn(make_float2(v0, v1));
                }
            }
        }
    }
}

// ===========================================================================
// Scatter: z[dst] += w * y16[src]  (fp16 gather, fp32 vector red atomics).
// ===========================================================================
__global__ __launch_bounds__(256) void scatter_kernel(
    const int* __restrict__ src, const int* __restrict__ dst,
    const float* __restrict__ ew, const __half* __restrict__ y16,
    float* __restrict__ z, int E)
{
    __shared__ int s_src[64], s_dst[64];
    __shared__ float s_w[64];
    const int base = blockIdx.x * 64;
    const int tid = threadIdx.x;
    if (tid < 64) {
        int e = base + tid;
        if (e < E) { s_src[tid] = src[e]; s_dst[tid] = dst[e]; s_w[tid] = ew[e]; }
    }
    __syncthreads();
    #pragma unroll
    for (int it = 0; it < 4; it++) {
        int idx = it * 256 + tid;
        int e = idx >> 4;
        int c = idx & 15;
        if (base + e < E) {
            float w = s_w[e];
            uint2 hv = *(const uint2*)(y16 + (size_t)s_src[e] * HDIM + c * 4);
            float2 f0 = __half22float2(*(__half2*)&hv.x);
            float2 f1 = __half22float2(*(__half2*)&hv.y);
            float4* p = (float4*)z + (size_t)s_dst[e] * 16 + c;
            asm volatile("red.global.add.v4.f32 [%0], {%1,%2,%3,%4};"
                         :: "l"(p), "f"(w * f0.x), "f"(w * f0.y),
                            "f"(w * f1.x), "f"(w * f1.y)
                         : "memory");
        }
    }
}

// ===========================================================================
// GEMM B: h2 = relu(z + ba) @ W + bb, BN stats into stat_set.
// tf32 mma, same tiling as gemm_a (K=64, BK=32).
// ===========================================================================
__global__ __launch_bounds__(256) void gemm_b_kernel(
    const float* __restrict__ Zin, const float* __restrict__ W,
    const float* __restrict__ ba, const float* __restrict__ bb,
    float* __restrict__ h2, int N, int stat_set)
{
    constexpr int K = HDIM, BM = 128, BK = 32;
    __shared__ __align__(16) float Ws[K][WPAD];
    __shared__ __align__(16) float AsT[BK][BM + 4];
    __shared__ float s_sum[HDIM], s_ssq[HDIM];

    const int tid = threadIdx.x;
    const int lane = tid & 31, wid = tid >> 5;
    const int g = lane >> 2, tig = lane & 3;
    const int warpM = wid & 3, warpN = wid >> 2;
    const int r0 = blockIdx.x * BM;

    if (tid < HDIM) { s_sum[tid] = 0.f; s_ssq[tid] = 0.f; }

    {
        #pragma unroll
        for (int i = tid; i < K * 16; i += 256) {
            int row = i >> 4, c4 = (i & 15) * 4;
            float4 v = *(const float4*)(W + (size_t)row * HDIM + c4);
            uint32_t u0, u1, u2, u3;
            TF32(u0, v.x); TF32(u1, v.y); TF32(u2, v.z); TF32(u3, v.w);
            float4 o = make_float4(__uint_as_float(u0), __uint_as_float(u1),
                                   __uint_as_float(u2), __uint_as_float(u3));
            *(float4*)&Ws[row][c4] = o;
        }
    }

    float acc[2][4][4];
    #pragma unroll
    for (int m = 0; m < 2; m++)
        #pragma unroll
        for (int j = 0; j < 4; j++)
            #pragma unroll
            for (int q = 0; q < 4; q++) acc[m][j][q] = 0.f;

    constexpr int LPI = BK / 8;
    constexpr int RG  = BK / 4;
    for (int kk = 0; kk < K; kk += BK) {
        __syncthreads();
        #pragma unroll
        for (int pp = 0; pp < LPI; pp++) {
            int row = (tid / RG) + pp * (256 / RG);
            int c4 = (tid % RG) * 4;
            int gr = r0 + row;
            float4 v = make_float4(0.f, 0.f, 0.f, 0.f);
            if (gr < N) {
                v = *(const float4*)(Zin + (size_t)gr * K + kk + c4);
                float4 b = *(const float4*)(ba + kk + c4);
                v.x = fmaxf(v.x + b.x, 0.f);
                v.y = fmaxf(v.y + b.y, 0.f);
                v.z = fmaxf(v.z + b.z, 0.f);
                v.w = fmaxf(v.w + b.w, 0.f);
            }
            uint32_t u0, u1, u2, u3;
            TF32(u0, v.x); TF32(u1, v.y); TF32(u2, v.z); TF32(u3, v.w);
            AsT[c4 + 0][row] = __uint_as_float(u0);
            AsT[c4 + 1][row] = __uint_as_float(u1);
            AsT[c4 + 2][row] = __uint_as_float(u2);
            AsT[c4 + 3][row] = __uint_as_float(u3);
        }
        __syncthreads();
        #pragma unroll
        for (int kc = 0; kc < BK / 8; kc++) {
            const int kl = kc * 8;
            uint32_t bf[4][2];
            #pragma unroll
            for (int j = 0; j < 4; j++) {
                int n = warpN * 32 + j * 8 + g;
                bf[j][0] = __float_as_uint(Ws[kk + kl + tig][n]);
                bf[j][1] = __float_as_uint(Ws[kk + kl + tig + 4][n]);
            }
            #pragma unroll
            for (int m = 0; m < 2; m++) {
                int rb = warpM * 32 + m * 16;
                uint32_t a0 = __float_as_uint(AsT[kl + tig][rb + g]);
                uint32_t a1 = __float_as_uint(AsT[kl + tig][rb + g + 8]);
                uint32_t a2 = __float_as_uint(AsT[kl + tig + 4][rb + g]);
                uint32_t a3 = __float_as_uint(AsT[kl + tig + 4][rb + g + 8]);
                #pragma unroll
                for (int j = 0; j < 4; j++)
                    MMA_TF32(acc[m][j], a0, a1, a2, a3, bf[j][0], bf[j][1]);
            }
        }
    }

    float csum[4][2], cssq[4][2];
    #pragma unroll
    for (int j = 0; j < 4; j++)
        #pragma unroll
        for (int q = 0; q < 2; q++) { csum[j][q] = 0.f; cssq[j][q] = 0.f; }

    #pragma unroll
    for (int m = 0; m < 2; m++) {
        #pragma unroll
        for (int half = 0; half < 2; half++) {
            int gr = r0 + warpM * 32 + m * 16 + g + half * 8;
            if (gr < N) {
                #pragma unroll
                for (int j = 0; j < 4; j++) {
                    int col = warpN * 32 + j * 8 + 2 * tig;
                    float v0 = acc[m][j][half * 2 + 0] + bb[col];
                    float v1 = acc[m][j][half * 2 + 1] + bb[col + 1];
                    *(float2*)(h2 + (size_t)gr * HDIM + col) = make_float2(v0, v1);
                    csum[j][0] += v0; cssq[j][0] += v0 * v0;
                    csum[j][1] += v1; cssq[j][1] += v1 * v1;
                }
            }
        }
    }
    __syncthreads();
    #pragma unroll
    for (int j = 0; j < 4; j++) {
        int col = warpN * 32 + j * 8 + 2 * tig;
        atomicAdd(&s_sum[col], csum[j][0]);
        atomicAdd(&s_ssq[col], cssq[j][0]);
        atomicAdd(&s_sum[col + 1], csum[j][1]);
        atomicAdd(&s_ssq[col + 1], cssq[j][1]);
    }
    __syncthreads();
    if (tid < HDIM) {
        atomicAdd(&g_sum[stat_set][tid], s_sum[tid]);
        atomicAdd(&g_sumsq[stat_set][tid], s_ssq[tid]);
    }
}

// ---------------------------------------------------------------------------
// Final BN apply + residual into d_out.
// ---------------------------------------------------------------------------
__global__ __launch_bounds__(256) void bn_apply_final_kernel(
    const float* __restrict__ h2, const float* __restrict__ hprev,
    float* __restrict__ out,
    const float* __restrict__ gamma, const float* __restrict__ beta,
    int stat_set, float invN, int N)
{
    __shared__ __align__(16) float s_scale[HDIM], s_shift[HDIM];
    const int tid = threadIdx.x;
    if (tid < HDIM) {
        float mean = g_sum[stat_set][tid] * invN;
        float var  = g_sumsq[stat_set][tid] * invN - mean * mean;
        float sc   = gamma[tid] * rsqrtf(var + BN_EPS);
        s_scale[tid] = sc;
        s_shift[tid] = beta[tid] - mean * sc;
    }
    __syncthreads();
    int idx = blockIdx.x * 256 + tid;
    if (idx >= N * 16) return;
    int c4 = (idx & 15) * 4;
    float4 v = ((const float4*)h2)[idx];
    float4 sc = *(const float4*)&s_scale[c4];
    float4 sh = *(const float4*)&s_shift[c4];
    float4 p = ((const float4*)hprev)[idx];
    v.x = p.x + fmaxf(fmaf(v.x, sc.x, sh.x), 0.f);
    v.y = p.y + fmaxf(fmaf(v.y, sc.y, sh.y), 0.f);
    v.z = p.z + fmaxf(fmaf(v.z, sc.z, sh.z), 0.f);
    v.w = p.w + fmaxf(fmaf(v.w, sc.w, sh.w), 0.f);
    ((float4*)out)[idx] = v;
}

// ---------------------------------------------------------------------------
// Host launcher
// ---------------------------------------------------------------------------
extern "C" void kernel_launch(void* const* d_in, const int* in_sizes, int n_in,
                              void* d_out, int out_size)
{
    const float* x    = (const float*)d_in[0];
    const int* ei     = (const int*)d_in[1];     // int32 (JAX x64 disabled)
    const float* ew   = (const float*)d_in[2];
    const float* eps1 = (const float*)d_in[3];
    const float* W1a  = (const float*)d_in[4];
    const float* b1a  = (const float*)d_in[5];
    const float* W1b  = (const float*)d_in[6];
    const float* b1b  = (const float*)d_in[7];
    const float* g1   = (const float*)d_in[8];
    const float* be1  = (const float*)d_in[9];
    const float* epss = (const float*)d_in[10];
    const float* Wsa  = (const float*)d_in[11];
    const float* bsa  = (const float*)d_in[12];
    const float* Wsb  = (const float*)d_in[13];
    const float* bsb  = (const float*)d_in[14];
    const float* gs   = (const float*)d_in[15];
    const float* bes  = (const float*)d_in[16];

    const int F   = in_sizes[4] / in_sizes[5];   // 128
    const int N   = in_sizes[0] / F;
    const int E   = in_sizes[2];
    const int Lm1 = in_sizes[10];

    const int* src = ei;
    const int* dst = ei + E;

    __half* yb;
    float *zb, *h2b, *hb;
    cudaGetSymbolAddress((void**)&yb,  g_y16);
    cudaGetSymbolAddress((void**)&zb,  g_z);
    cudaGetSymbolAddress((void**)&h2b, g_h2);
    cudaGetSymbolAddress((void**)&hb,  g_h);

    const int gemm_blocks = (N + 127) / 128;
    const int scat_blocks = (E + 63) / 64;
    const int bn_blocks   = (N * 16 + 255) / 256;
    const float invN = 1.0f / (float)N;

    // -------- Layer 0 (K = F = 128): GEMM-first --------
    gemm_a_kernel<128, false><<<gemm_blocks, 256>>>(
        x, W1a, eps1, 0, nullptr, nullptr, 0, 0, invN, /*zero_stats=*/1,
        nullptr, yb, zb, N);
    scatter_kernel<<<scat_blocks, 256>>>(src, dst, ew, yb, zb, E);
    gemm_b_kernel<<<gemm_blocks, 256>>>(zb, W1b, b1a, b1b, h2b, N, /*set*/0);

    // -------- Hidden layers: previous BN fused into A-load --------
    for (int i = 0; i < Lm1; i++) {
        const float* gam = (i == 0) ? g1  : gs  + (size_t)(i - 1) * HDIM;
        const float* bet = (i == 0) ? be1 : bes + (size_t)(i - 1) * HDIM;
        gemm_a_kernel<64, true><<<gemm_blocks, 256>>>(
            h2b, Wsa + (size_t)i * HDIM * HDIM, epss, i,
            gam, bet, /*stat_set=*/i, /*residual=*/(i > 0), invN, 0,
            hb, yb, zb, N);
        scatter_kernel<<<scat_blocks, 256>>>(src, dst, ew, yb, zb, E);
        gemm_b_kernel<<<gemm_blocks, 256>>>(
            zb, Wsb + (size_t)i * HDIM * HDIM,
            bsa + (size_t)i * HDIM, bsb + (size_t)i * HDIM,
            h2b, N, /*set*/i + 1);
    }

    // -------- Final BN + residual into d_out --------
    bn_apply_final_kernel<<<bn_blocks, 256>>>(
        h2b, hb, (float*)d_out,
        gs + (size_t)(Lm1 - 1) * HDIM, bes + (size_t)(Lm1 - 1) * HDIM,
        /*stat_set=*/Lm1, invN, N);
}

// round 14
// speedup vs baseline: 1.0909x; 1.0909x over previous
#include <cuda_runtime.h>
#include <cuda_fp16.h>
#include <cstdint>

#define HDIM 64
#define BN_EPS 1e-5f
#define MAXN 131072
#define MAXL 4

// Scratch (device globals — no allocation allowed). 16B-aligned.
__device__ __align__(16) __half g_y16[MAXN * HDIM]; // y = h @ Wa (fp16 gather)
__device__ __align__(16) float g_z[MAXN * HDIM];    // z = (1+eps)*y + scatter
__device__ __align__(16) float g_h2[MAXN * HDIM];   // pre-BN output of MLP
__device__ __align__(16) float g_h[MAXN * HDIM];    // residual stream
__device__ __align__(16) float g_sum[MAXL][HDIM];   // per-layer BN stats
__device__ __align__(16) float g_sumsq[MAXL][HDIM];

// Packed fp32x2 helpers (Blackwell FFMA2 path)
#define PACK2(out, lo, hi) \
    asm("mov.b64 %0, {%1, %2};" : "=l"(out) : "f"(lo), "f"(hi))
#define UNPACK2(lo, hi, in) \
    asm("mov.b64 {%0, %1}, %2;" : "=f"(lo), "=f"(hi) : "l"(in))
#define FMA2(acc, a, b) \
    asm("fma.rn.f32x2 %0, %1, %2, %0;" : "+l"(acc) : "l"(a), "l"(b))

// tf32 helpers
#define TF32(u, f) asm("cvt.rna.tf32.f32 %0, %1;" : "=r"(u) : "f"(f))
#define MMA_TF32(d, a0, a1, a2, a3, b0, b1) \
    asm volatile("mma.sync.aligned.m16n8k8.row.col.f32.tf32.tf32.f32 " \
        "{%0,%1,%2,%3}, {%4,%5,%6,%7}, {%8,%9}, {%0,%1,%2,%3};" \
        : "+f"(d[0]), "+f"(d[1]), "+f"(d[2]), "+f"(d[3]) \
        : "r"(a0), "r"(a1), "r"(a2), "r"(a3), "r"(b0), "r"(b1))

#define WPAD 72   // Ws row stride in floats (conflict-free B-frag loads)

// ===========================================================================
// GEMM A (tf32 MMA, K=64, FUSE) — R13-proven: 26.7us vs SIMT 31.6us.
// BM=128, 256 thr (8 warps 4x2), m16n8k8, fp32 accum. BK=32.
// y16 = A' @ W (fp16), z = (1+eps)*(A' @ W) (fp32).
// A' = [residual +] relu(BN(h2)) on the fly, written to hbuf (fp32).
// ===========================================================================
__global__ __launch_bounds__(256) void gemm_a_mma_kernel(
    const float* __restrict__ A, const float* __restrict__ W,
    const float* __restrict__ eps_ptr, int eps_idx,
    const float* __restrict__ gamma, const float* __restrict__ beta,
    int stat_set, int residual, float invN,
    float* __restrict__ hbuf, __half* __restrict__ y16,
    float* __restrict__ z, int N)
{
    constexpr int K = 64, BM = 128, BK = 32;
    __shared__ __align__(16) float Ws[K][WPAD];
    __shared__ __align__(16) float AsT[BK][BM + 4];
    __shared__ __align__(16) float s_scale[HDIM], s_shift[HDIM];

    const int tid = threadIdx.x;
    const int lane = tid & 31, wid = tid >> 5;
    const int g = lane >> 2, tig = lane & 3;
    const int warpM = wid & 3, warpN = wid >> 2;
    const int r0 = blockIdx.x * BM;

    if (tid < HDIM) {
        float mean = g_sum[stat_set][tid] * invN;
        float var  = g_sumsq[stat_set][tid] * invN - mean * mean;
        float sc   = gamma[tid] * rsqrtf(var + BN_EPS);
        s_scale[tid] = sc;
        s_shift[tid] = beta[tid] - mean * sc;
    }

    {   // stage W, tf32-rounded, padded rows
        #pragma unroll
        for (int i = tid; i < K * 16; i += 256) {
            int row = i >> 4, c4 = (i & 15) * 4;
            float4 v = *(const float4*)(W + (size_t)row * HDIM + c4);
            uint32_t u0, u1, u2, u3;
            TF32(u0, v.x); TF32(u1, v.y); TF32(u2, v.z); TF32(u3, v.w);
            *(float4*)&Ws[row][c4] =
                make_float4(__uint_as_float(u0), __uint_as_float(u1),
                            __uint_as_float(u2), __uint_as_float(u3));
        }
    }

    float acc[2][4][4];
    #pragma unroll
    for (int m = 0; m < 2; m++)
        #pragma unroll
        for (int j = 0; j < 4; j++)
            #pragma unroll
            for (int q = 0; q < 4; q++) acc[m][j][q] = 0.f;

    constexpr int LPI = BK / 8;
    constexpr int RG  = BK / 4;
    for (int kk = 0; kk < K; kk += BK) {
        __syncthreads();                 // covers s_scale/Ws init on first trip
        #pragma unroll
        for (int pp = 0; pp < LPI; pp++) {
            int row = (tid / RG) + pp * (256 / RG);
            int c4 = (tid % RG) * 4;
            int gr = r0 + row;
            float4 v = make_float4(0.f, 0.f, 0.f, 0.f);
            if (gr < N) {
                v = *(const float4*)(A + (size_t)gr * K + kk + c4);
                float4 sc = *(const float4*)&s_scale[kk + c4];
                float4 sh = *(const float4*)&s_shift[kk + c4];
                v.x = fmaxf(fmaf(v.x, sc.x, sh.x), 0.f);
                v.y = fmaxf(fmaf(v.y, sc.y, sh.y), 0.f);
                v.z = fmaxf(fmaf(v.z, sc.z, sh.z), 0.f);
                v.w = fmaxf(fmaf(v.w, sc.w, sh.w), 0.f);
                float* hp = hbuf + (size_t)gr * K + kk + c4;
                if (residual) {
                    float4 h = *(const float4*)hp;
                    v.x += h.x; v.y += h.y; v.z += h.z; v.w += h.w;
                }
                *(float4*)hp = v;        // full fp32 residual stream
            }
            uint32_t u0, u1, u2, u3;
            TF32(u0, v.x); TF32(u1, v.y); TF32(u2, v.z); TF32(u3, v.w);
            AsT[c4 + 0][row] = __uint_as_float(u0);
            AsT[c4 + 1][row] = __uint_as_float(u1);
            AsT[c4 + 2][row] = __uint_as_float(u2);
            AsT[c4 + 3][row] = __uint_as_float(u3);
        }
        __syncthreads();
        #pragma unroll
        for (int kc = 0; kc < BK / 8; kc++) {
            const int kl = kc * 8;
            uint32_t bf[4][2];
            #pragma unroll
            for (int j = 0; j < 4; j++) {
                int n = warpN * 32 + j * 8 + g;
                bf[j][0] = __float_as_uint(Ws[kk + kl + tig][n]);
                bf[j][1] = __float_as_uint(Ws[kk + kl + tig + 4][n]);
            }
            #pragma unroll
            for (int m = 0; m < 2; m++) {
                int rb = warpM * 32 + m * 16;
                uint32_t a0 = __float_as_uint(AsT[kl + tig][rb + g]);
                uint32_t a1 = __float_as_uint(AsT[kl + tig][rb + g + 8]);
                uint32_t a2 = __float_as_uint(AsT[kl + tig + 4][rb + g]);
                uint32_t a3 = __float_as_uint(AsT[kl + tig + 4][rb + g + 8]);
                #pragma unroll
                for (int j = 0; j < 4; j++)
                    MMA_TF32(acc[m][j], a0, a1, a2, a3, bf[j][0], bf[j][1]);
            }
        }
    }

    const float ep = 1.0f + eps_ptr[eps_idx];
    #pragma unroll
    for (int m = 0; m < 2; m++) {
        #pragma unroll
        for (int half = 0; half < 2; half++) {
            int gr = r0 + warpM * 32 + m * 16 + g + half * 8;
            if (gr < N) {
                #pragma unroll
                for (int j = 0; j < 4; j++) {
                    int col = warpN * 32 + j * 8 + 2 * tig;
                    float v0 = acc[m][j][half * 2 + 0];
                    float v1 = acc[m][j][half * 2 + 1];
                    *(float2*)(z + (size_t)gr * HDIM + col) =
                        make_float2(v0 * ep, v1 * ep);
                    *(__half2*)(y16 + (size_t)gr * HDIM + col) =
                        __float22half2_rn(make_float2(v0, v1));
                }
            }
        }
    }
}

// ===========================================================================
// GEMM A layer-0 (SIMT FFMA2, K=128, no FUSE) — R12-proven.
// BM=128, BK=16, 8x4 microtile.
// ===========================================================================
__global__ __launch_bounds__(256) void gemm_a0_kernel(
    const float* __restrict__ A, const float* __restrict__ W,
    const float* __restrict__ eps_ptr,
    __half* __restrict__ y16, float* __restrict__ z, int N)
{
    constexpr int K = 128, BM = 128, BK = 16;
    __shared__ __align__(16) float Ws[K][HDIM];
    __shared__ __align__(16) float AsT[BK][BM + 4];

    const int tid = threadIdx.x;
    const int tx = tid & 15;
    const int ty = tid >> 4;
    const int r0 = blockIdx.x * BM;

    if (blockIdx.x == 0 && tid < HDIM) {
        #pragma unroll
        for (int s = 0; s < MAXL; s++) { g_sum[s][tid] = 0.f; g_sumsq[s][tid] = 0.f; }
    }

    {
        const float4* W4 = (const float4*)W;
        float4* Ws4 = (float4*)&Ws[0][0];
        #pragma unroll
        for (int i = tid; i < K * HDIM / 4; i += 256) Ws4[i] = W4[i];
    }

    unsigned long long accp[4][4];
    #pragma unroll
    for (int p = 0; p < 4; p++)
        #pragma unroll
        for (int j = 0; j < 4; j++) accp[p][j] = 0ull;

    for (int kk = 0; kk < K; kk += BK) {
        __syncthreads();
        #pragma unroll
        for (int pp = 0; pp < 2; pp++) {
            int row = (tid >> 2) + pp * 64;
            int c4 = (tid & 3) * 4;
            int gr = r0 + row;
            float4 v = make_float4(0.f, 0.f, 0.f, 0.f);
            if (gr < N) v = *(const float4*)(A + (size_t)gr * K + kk + c4);
            AsT[c4 + 0][row] = v.x;
            AsT[c4 + 1][row] = v.y;
            AsT[c4 + 2][row] = v.z;
            AsT[c4 + 3][row] = v.w;
        }
        __syncthreads();
        #pragma unroll
        for (int k = 0; k < BK; k++) {
            float4 bv = *(const float4*)&Ws[kk + k][tx * 4];
            unsigned long long b0, b1, b2, b3;
            PACK2(b0, bv.x, bv.x); PACK2(b1, bv.y, bv.y);
            PACK2(b2, bv.z, bv.z); PACK2(b3, bv.w, bv.w);
            const unsigned long long* ap =
                (const unsigned long long*)&AsT[k][ty * 8];
            #pragma unroll
            for (int p = 0; p < 4; p++) {
                unsigned long long a = ap[p];
                FMA2(accp[p][0], a, b0);
                FMA2(accp[p][1], a, b1);
                FMA2(accp[p][2], a, b2);
                FMA2(accp[p][3], a, b3);
            }
        }
    }

    const float ep = 1.0f + eps_ptr[0];
    #pragma unroll
    for (int p = 0; p < 4; p++) {
        float lo0, hi0, lo1, hi1, lo2, hi2, lo3, hi3;
        UNPACK2(lo0, hi0, accp[p][0]);
        UNPACK2(lo1, hi1, accp[p][1]);
        UNPACK2(lo2, hi2, accp[p][2]);
        UNPACK2(lo3, hi3, accp[p][3]);
        int gr = r0 + ty * 8 + 2 * p;
        if (gr < N) {
            __half2 hh[2];
            hh[0] = __float22half2_rn(make_float2(lo0, lo1));
            hh[1] = __float22half2_rn(make_float2(lo2, lo3));
            *(uint2*)(y16 + (size_t)gr * HDIM + tx * 4) = *(uint2*)hh;
            ((float4*)z)[(size_t)gr * 16 + tx] =
                make_float4(lo0 * ep, lo1 * ep, lo2 * ep, lo3 * ep);
        }
        if (gr + 1 < N) {
            __half2 hh[2];
            hh[0] = __float22half2_rn(make_float2(hi0, hi1));
            hh[1] = __float22half2_rn(make_float2(hi2, hi3));
            *(uint2*)(y16 + (size_t)(gr + 1) * HDIM + tx * 4) = *(uint2*)hh;
            ((float4*)z)[(size_t)(gr + 1) * 16 + tx] =
                make_float4(hi0 * ep, hi1 * ep, hi2 * ep, hi3 * ep);
        }
    }
}

// ===========================================================================
// Scatter: z[dst] += w * y16[src]  (fp16 gather, fp32 vector red atomics).
// ===========================================================================
__global__ __launch_bounds__(256) void scatter_kernel(
    const int* __restrict__ src, const int* __restrict__ dst,
    const float* __restrict__ ew, const __half* __restrict__ y16,
    float* __restrict__ z, int E)
{
    __shared__ int s_src[64], s_dst[64];
    __shared__ float s_w[64];
    const int base = blockIdx.x * 64;
    const int tid = threadIdx.x;
    if (tid < 64) {
        int e = base + tid;
        if (e < E) { s_src[tid] = src[e]; s_dst[tid] = dst[e]; s_w[tid] = ew[e]; }
    }
    __syncthreads();
    #pragma unroll
    for (int it = 0; it < 4; it++) {
        int idx = it * 256 + tid;
        int e = idx >> 4;
        int c = idx & 15;
        if (base + e < E) {
            float w = s_w[e];
            uint2 hv = *(const uint2*)(y16 + (size_t)s_src[e] * HDIM + c * 4);
            float2 f0 = __half22float2(*(__half2*)&hv.x);
            float2 f1 = __half22float2(*(__half2*)&hv.y);
            float4* p = (float4*)z + (size_t)s_dst[e] * 16 + c;
            asm volatile("red.global.add.v4.f32 [%0], {%1,%2,%3,%4};"
                         :: "l"(p), "f"(w * f0.x), "f"(w * f0.y),
                            "f"(w * f1.x), "f"(w * f1.y)
                         : "memory");
        }
    }
}

// ===========================================================================
// GEMM B (SIMT FFMA2, R12-proven): h2 = relu(z + ba) @ W + bb, BN stats.
// BM=128, BK=32, 8x4 microtile, coalesced float4 epilogue.
// ===========================================================================
__global__ __launch_bounds__(256) void gemm_b_kernel(
    const float* __restrict__ Zin, const float* __restrict__ W,
    const float* __restrict__ ba, const float* __restrict__ bb,
    float* __restrict__ h2, int N, int stat_set)
{
    constexpr int K = HDIM, BM = 128, BK = 32;
    __shared__ __align__(16) float Ws[K][HDIM];
    __shared__ __align__(16) float AsT[BK][BM + 4];
    __shared__ float s_sum[HDIM], s_ssq[HDIM];

    const int tid = threadIdx.x;
    const int tx = tid & 15;
    const int ty = tid >> 4;
    const int r0 = blockIdx.x * BM;

    if (tid < HDIM) { s_sum[tid] = 0.f; s_ssq[tid] = 0.f; }

    {
        const float4* W4 = (const float4*)W;
        float4* Ws4 = (float4*)&Ws[0][0];
        #pragma unroll
        for (int i = tid; i < K * HDIM / 4; i += 256) Ws4[i] = W4[i];
    }

    unsigned long long accp[4][4];
    #pragma unroll
    for (int p = 0; p < 4; p++)
        #pragma unroll
        for (int j = 0; j < 4; j++) accp[p][j] = 0ull;

    constexpr int LPI = BK / 8;
    constexpr int RG  = BK / 4;
    for (int kk = 0; kk < K; kk += BK) {
        __syncthreads();
        #pragma unroll
        for (int pp = 0; pp < LPI; pp++) {
            int row = (tid / RG) + pp * (256 / RG);
            int c4 = (tid % RG) * 4;
            int gr = r0 + row;
            float4 v = make_float4(0.f, 0.f, 0.f, 0.f);
            if (gr < N) {
                v = *(const float4*)(Zin + (size_t)gr * K + kk + c4);
                float4 b = *(const float4*)(ba + kk + c4);
                v.x = fmaxf(v.x + b.x, 0.f);
                v.y = fmaxf(v.y + b.y, 0.f);
                v.z = fmaxf(v.z + b.z, 0.f);
                v.w = fmaxf(v.w + b.w, 0.f);
            }
            AsT[c4 + 0][row] = v.x;
            AsT[c4 + 1][row] = v.y;
            AsT[c4 + 2][row] = v.z;
            AsT[c4 + 3][row] = v.w;
        }
        __syncthreads();
        #pragma unroll
        for (int k = 0; k < BK; k++) {
            float4 bv = *(const float4*)&Ws[kk + k][tx * 4];
            unsigned long long b0, b1, b2, b3;
            PACK2(b0, bv.x, bv.x); PACK2(b1, bv.y, bv.y);
            PACK2(b2, bv.z, bv.z); PACK2(b3, bv.w, bv.w);
            const unsigned long long* ap =
                (const unsigned long long*)&AsT[k][ty * 8];
            #pragma unroll
            for (int p = 0; p < 4; p++) {
                unsigned long long a = ap[p];
                FMA2(accp[p][0], a, b0);
                FMA2(accp[p][1], a, b1);
                FMA2(accp[p][2], a, b2);
                FMA2(accp[p][3], a, b3);
            }
        }
    }

    const float4 bb4 = *(const float4*)(bb + tx * 4);
    float csum[4] = {0.f, 0.f, 0.f, 0.f};
    float cssq[4] = {0.f, 0.f, 0.f, 0.f};
    #pragma unroll
    for (int p = 0; p < 4; p++) {
        float lo0, hi0, lo1, hi1, lo2, hi2, lo3, hi3;
        UNPACK2(lo0, hi0, accp[p][0]);
        UNPACK2(lo1, hi1, accp[p][1]);
        UNPACK2(lo2, hi2, accp[p][2]);
        UNPACK2(lo3, hi3, accp[p][3]);
        int gr = r0 + ty * 8 + 2 * p;
        if (gr < N) {
            float4 o = make_float4(lo0 + bb4.x, lo1 + bb4.y,
                                   lo2 + bb4.z, lo3 + bb4.w);
            ((float4*)h2)[(size_t)gr * 16 + tx] = o;
            csum[0] += o.x; cssq[0] += o.x * o.x;
            csum[1] += o.y; cssq[1] += o.y * o.y;
            csum[2] += o.z; cssq[2] += o.z * o.z;
            csum[3] += o.w; cssq[3] += o.w * o.w;
        }
        if (gr + 1 < N) {
            float4 o = make_float4(hi0 + bb4.x, hi1 + bb4.y,
                                   hi2 + bb4.z, hi3 + bb4.w);
            ((float4*)h2)[(size_t)(gr + 1) * 16 + tx] = o;
            csum[0] += o.x; cssq[0] += o.x * o.x;
            csum[1] += o.y; cssq[1] += o.y * o.y;
            csum[2] += o.z; cssq[2] += o.z * o.z;
            csum[3] += o.w; cssq[3] += o.w * o.w;
        }
    }
    __syncthreads();
    #pragma unroll
    for (int j = 0; j < 4; j++) {
        atomicAdd(&s_sum[tx * 4 + j], csum[j]);
        atomicAdd(&s_ssq[tx * 4 + j], cssq[j]);
    }
    __syncthreads();
    if (tid < HDIM) {
        atomicAdd(&g_sum[stat_set][tid], s_sum[tid]);
        atomicAdd(&g_sumsq[stat_set][tid], s_ssq[tid]);
    }
}

// ---------------------------------------------------------------------------
// Final BN apply + residual into d_out.
// ---------------------------------------------------------------------------
__global__ __launch_bounds__(256) void bn_apply_final_kernel(
    const float* __restrict__ h2, const float* __restrict__ hprev,
    float* __restrict__ out,
    const float* __restrict__ gamma, const float* __restrict__ beta,
    int stat_set, float invN, int N)
{
    __shared__ __align__(16) float s_scale[HDIM], s_shift[HDIM];
    const int tid = threadIdx.x;
    if (tid < HDIM) {
        float mean = g_sum[stat_set][tid] * invN;
        float var  = g_sumsq[stat_set][tid] * invN - mean * mean;
        float sc   = gamma[tid] * rsqrtf(var + BN_EPS);
        s_scale[tid] = sc;
        s_shift[tid] = beta[tid] - mean * sc;
    }
    __syncthreads();
    int idx = blockIdx.x * 256 + tid;
    if (idx >= N * 16) return;
    int c4 = (idx & 15) * 4;
    float4 v = ((const float4*)h2)[idx];
    float4 sc = *(const float4*)&s_scale[c4];
    float4 sh = *(const float4*)&s_shift[c4];
    float4 p = ((const float4*)hprev)[idx];
    v.x = p.x + fmaxf(fmaf(v.x, sc.x, sh.x), 0.f);
    v.y = p.y + fmaxf(fmaf(v.y, sc.y, sh.y), 0.f);
    v.z = p.z + fmaxf(fmaf(v.z, sc.z, sh.z), 0.f);
    v.w = p.w + fmaxf(fmaf(v.w, sc.w, sh.w), 0.f);
    ((float4*)out)[idx] = v;
}

// ---------------------------------------------------------------------------
// Host launcher
// ---------------------------------------------------------------------------
extern "C" void kernel_launch(void* const* d_in, const int* in_sizes, int n_in,
                              void* d_out, int out_size)
{
    const float* x    = (const float*)d_in[0];
    const int* ei     = (const int*)d_in[1];     // int32 (JAX x64 disabled)
    const float* ew   = (const float*)d_in[2];
    const float* eps1 = (const float*)d_in[3];
    const float* W1a  = (const float*)d_in[4];
    const float* b1a  = (const float*)d_in[5];
    const float* W1b  = (const float*)d_in[6];
    const float* b1b  = (const float*)d_in[7];
    const float* g1   = (const float*)d_in[8];
    const float* be1  = (const float*)d_in[9];
    const float* epss = (const float*)d_in[10];
    const float* Wsa  = (const float*)d_in[11];
    const float* bsa  = (const float*)d_in[12];
    const float* Wsb  = (const float*)d_in[13];
    const float* bsb  = (const float*)d_in[14];
    const float* gs   = (const float*)d_in[15];
    const float* bes  = (const float*)d_in[16];

    const int F   = in_sizes[4] / in_sizes[5];   // 128
    const int N   = in_sizes[0] / F;
    const int E   = in_sizes[2];
    const int Lm1 = in_sizes[10];

    const int* src = ei;
    const int* dst = ei + E;

    __half* yb;
    float *zb, *h2b, *hb;
    cudaGetSymbolAddress((void**)&yb,  g_y16);
    cudaGetSymbolAddress((void**)&zb,  g_z);
    cudaGetSymbolAddress((void**)&h2b, g_h2);
    cudaGetSymbolAddress((void**)&hb,  g_h);

    const int gemm_blocks = (N + 127) / 128;
    const int scat_blocks = (E + 63) / 64;
    const int bn_blocks   = (N * 16 + 255) / 256;
    const float invN = 1.0f / (float)N;

    // -------- Layer 0 (K = F = 128): SIMT GEMM-first --------
    gemm_a0_kernel<<<gemm_blocks, 256>>>(x, W1a, eps1, yb, zb, N);
    scatter_kernel<<<scat_blocks, 256>>>(src, dst, ew, yb, zb, E);
    gemm_b_kernel<<<gemm_blocks, 256>>>(zb, W1b, b1a, b1b, h2b, N, /*set*/0);

    // -------- Hidden layers: tf32 MMA gemm_a (BN fused), SIMT gemm_b --------
    for (int i = 0; i < Lm1; i++) {
        const float* gam = (i == 0) ? g1  : gs  + (size_t)(i - 1) * HDIM;
        const float* bet = (i == 0) ? be1 : bes + (size_t)(i - 1) * HDIM;
        gemm_a_mma_kernel<<<gemm_blocks, 256>>>(
            h2b, Wsa + (size_t)i * HDIM * HDIM, epss, i,
            gam, bet, /*stat_set=*/i, /*residual=*/(i > 0), invN,
            hb, yb, zb, N);
        scatter_kernel<<<scat_blocks, 256>>>(src, dst, ew, yb, zb, E);
        gemm_b_kernel<<<gemm_blocks, 256>>>(
            zb, Wsb + (size_t)i * HDIM * HDIM,
            bsa + (size_t)i * HDIM, bsb + (size_t)i * HDIM,
            h2b, N, /*set*/i + 1);
    }

    // -------- Final BN + residual into d_out --------
    bn_apply_final_kernel<<<bn_blocks, 256>>>(
        h2b, hb, (float*)d_out,
        gs + (size_t)(Lm1 - 1) * HDIM, bes + (size_t)(Lm1 - 1) * HDIM,
        /*stat_set=*/Lm1, invN, N);
}

// round 15
// speedup vs baseline: 1.1766x; 1.0785x over previous
#include <cuda_runtime.h>
#include <cuda_fp16.h>
#include <cstdint>

#define HDIM 64
#define BN_EPS 1e-5f
#define MAXN 131072
#define MAXL 4

// Scratch (device globals — no allocation allowed). 16B-aligned.
__device__ __align__(16) __half g_y16[MAXN * HDIM]; // y = h @ Wa (fp16 gather)
__device__ __align__(16) float g_z[MAXN * HDIM];    // z = (1+eps)*y + scatter
__device__ __align__(16) float g_h2[MAXN * HDIM];   // pre-BN output of MLP
__device__ __align__(16) float g_h[MAXN * HDIM];    // residual stream
__device__ __align__(16) float g_sum[MAXL][HDIM];   // per-layer BN stats
__device__ __align__(16) float g_sumsq[MAXL][HDIM];

// tf32 helpers
#define TF32(u, f) asm("cvt.rna.tf32.f32 %0, %1;" : "=r"(u) : "f"(f))
#define MMA_TF32(d, a0, a1, a2, a3, b0, b1) \
    asm volatile("mma.sync.aligned.m16n8k8.row.col.f32.tf32.tf32.f32 " \
        "{%0,%1,%2,%3}, {%4,%5,%6,%7}, {%8,%9}, {%0,%1,%2,%3};" \
        : "+f"(d[0]), "+f"(d[1]), "+f"(d[2]), "+f"(d[3]) \
        : "r"(a0), "r"(a1), "r"(a2), "r"(a3), "r"(b0), "r"(b1))

#define WPAD 72   // Ws row stride in floats (conflict-free B-frag loads)

// ===========================================================================
// GEMM A (tf32 MMA, K=64, FUSE) — R13/R14-proven: 26.8us.
// BM=128, 256 thr (8 warps 4x2), m16n8k8, fp32 accum, BK=32.
// y16 = A' @ W (fp16), z = (1+eps)*(A' @ W) (fp32).
// A' = [residual +] relu(BN(h2)) on the fly, written to hbuf (fp32).
// ===========================================================================
__global__ __launch_bounds__(256) void gemm_a_mma_kernel(
    const float* __restrict__ A, const float* __restrict__ W,
    const float* __restrict__ eps_ptr, int eps_idx,
    const float* __restrict__ gamma, const float* __restrict__ beta,
    int stat_set, int residual, float invN,
    float* __restrict__ hbuf, __half* __restrict__ y16,
    float* __restrict__ z, int N)
{
    constexpr int K = 64, BM = 128, BK = 32;
    __shared__ __align__(16) float Ws[K][WPAD];
    __shared__ __align__(16) float AsT[BK][BM + 4];
    __shared__ __align__(16) float s_scale[HDIM], s_shift[HDIM];

    const int tid = threadIdx.x;
    const int lane = tid & 31, wid = tid >> 5;
    const int g = lane >> 2, tig = lane & 3;
    const int warpM = wid & 3, warpN = wid >> 2;
    const int r0 = blockIdx.x * BM;

    if (tid < HDIM) {
        float mean = g_sum[stat_set][tid] * invN;
        float var  = g_sumsq[stat_set][tid] * invN - mean * mean;
        float sc   = gamma[tid] * rsqrtf(var + BN_EPS);
        s_scale[tid] = sc;
        s_shift[tid] = beta[tid] - mean * sc;
    }

    {   // stage W, tf32-rounded, padded rows
        #pragma unroll
        for (int i = tid; i < K * 16; i += 256) {
            int row = i >> 4, c4 = (i & 15) * 4;
            float4 v = *(const float4*)(W + (size_t)row * HDIM + c4);
            uint32_t u0, u1, u2, u3;
            TF32(u0, v.x); TF32(u1, v.y); TF32(u2, v.z); TF32(u3, v.w);
            *(float4*)&Ws[row][c4] =
                make_float4(__uint_as_float(u0), __uint_as_float(u1),
                            __uint_as_float(u2), __uint_as_float(u3));
        }
    }

    float acc[2][4][4];
    #pragma unroll
    for (int m = 0; m < 2; m++)
        #pragma unroll
        for (int j = 0; j < 4; j++)
            #pragma unroll
            for (int q = 0; q < 4; q++) acc[m][j][q] = 0.f;

    constexpr int LPI = BK / 8;
    constexpr int RG  = BK / 4;
    for (int kk = 0; kk < K; kk += BK) {
        __syncthreads();                 // covers s_scale/Ws init on first trip
        #pragma unroll
        for (int pp = 0; pp < LPI; pp++) {
            int row = (tid / RG) + pp * (256 / RG);
            int c4 = (tid % RG) * 4;
            int gr = r0 + row;
            float4 v = make_float4(0.f, 0.f, 0.f, 0.f);
            if (gr < N) {
                v = *(const float4*)(A + (size_t)gr * K + kk + c4);
                float4 sc = *(const float4*)&s_scale[kk + c4];
                float4 sh = *(const float4*)&s_shift[kk + c4];
                v.x = fmaxf(fmaf(v.x, sc.x, sh.x), 0.f);
                v.y = fmaxf(fmaf(v.y, sc.y, sh.y), 0.f);
                v.z = fmaxf(fmaf(v.z, sc.z, sh.z), 0.f);
                v.w = fmaxf(fmaf(v.w, sc.w, sh.w), 0.f);
                float* hp = hbuf + (size_t)gr * K + kk + c4;
                if (residual) {
                    float4 h = *(const float4*)hp;
                    v.x += h.x; v.y += h.y; v.z += h.z; v.w += h.w;
                }
                *(float4*)hp = v;        // full fp32 residual stream
            }
            uint32_t u0, u1, u2, u3;
            TF32(u0, v.x); TF32(u1, v.y); TF32(u2, v.z); TF32(u3, v.w);
            AsT[c4 + 0][row] = __uint_as_float(u0);
            AsT[c4 + 1][row] = __uint_as_float(u1);
            AsT[c4 + 2][row] = __uint_as_float(u2);
            AsT[c4 + 3][row] = __uint_as_float(u3);
        }
        __syncthreads();
        #pragma unroll
        for (int kc = 0; kc < BK / 8; kc++) {
            const int kl = kc * 8;
            uint32_t bf[4][2];
            #pragma unroll
            for (int j = 0; j < 4; j++) {
                int n = warpN * 32 + j * 8 + g;
                bf[j][0] = __float_as_uint(Ws[kk + kl + tig][n]);
                bf[j][1] = __float_as_uint(Ws[kk + kl + tig + 4][n]);
            }
            #pragma unroll
            for (int m = 0; m < 2; m++) {
                int rb = warpM * 32 + m * 16;
                uint32_t a0 = __float_as_uint(AsT[kl + tig][rb + g]);
                uint32_t a1 = __float_as_uint(AsT[kl + tig][rb + g + 8]);
                uint32_t a2 = __float_as_uint(AsT[kl + tig + 4][rb + g]);
                uint32_t a3 = __float_as_uint(AsT[kl + tig + 4][rb + g + 8]);
                #pragma unroll
                for (int j = 0; j < 4; j++)
                    MMA_TF32(acc[m][j], a0, a1, a2, a3, bf[j][0], bf[j][1]);
            }
        }
    }

    const float ep = 1.0f + eps_ptr[eps_idx];
    #pragma unroll
    for (int m = 0; m < 2; m++) {
        #pragma unroll
        for (int half = 0; half < 2; half++) {
            int gr = r0 + warpM * 32 + m * 16 + g + half * 8;
            if (gr < N) {
                #pragma unroll
                for (int j = 0; j < 4; j++) {
                    int col = warpN * 32 + j * 8 + 2 * tig;
                    float v0 = acc[m][j][half * 2 + 0];
                    float v1 = acc[m][j][half * 2 + 1];
                    *(float2*)(z + (size_t)gr * HDIM + col) =
                        make_float2(v0 * ep, v1 * ep);
                    *(__half2*)(y16 + (size_t)gr * HDIM + col) =
                        __float22half2_rn(make_float2(v0, v1));
                }
            }
        }
    }
}

// ===========================================================================
// GEMM A layer-0 (tf32 MMA, K=128, no FUSE): same structure, BK=16.
// Smem: Ws 36.9K + AsT 8.4K = 45.3K < 48K. Block 0 zeroes BN stat sets.
// ===========================================================================
__global__ __launch_bounds__(256) void gemm_a0_mma_kernel(
    const float* __restrict__ A, const float* __restrict__ W,
    const float* __restrict__ eps_ptr,
    __half* __restrict__ y16, float* __restrict__ z, int N)
{
    constexpr int K = 128, BM = 128, BK = 16;
    __shared__ __align__(16) float Ws[K][WPAD];
    __shared__ __align__(16) float AsT[BK][BM + 4];

    const int tid = threadIdx.x;
    const int lane = tid & 31, wid = tid >> 5;
    const int g = lane >> 2, tig = lane & 3;
    const int warpM = wid & 3, warpN = wid >> 2;
    const int r0 = blockIdx.x * BM;

    if (blockIdx.x == 0 && tid < HDIM) {
        #pragma unroll
        for (int s = 0; s < MAXL; s++) { g_sum[s][tid] = 0.f; g_sumsq[s][tid] = 0.f; }
    }

    {
        #pragma unroll
        for (int i = tid; i < K * 16; i += 256) {
            int row = i >> 4, c4 = (i & 15) * 4;
            float4 v = *(const float4*)(W + (size_t)row * HDIM + c4);
            uint32_t u0, u1, u2, u3;
            TF32(u0, v.x); TF32(u1, v.y); TF32(u2, v.z); TF32(u3, v.w);
            *(float4*)&Ws[row][c4] =
                make_float4(__uint_as_float(u0), __uint_as_float(u1),
                            __uint_as_float(u2), __uint_as_float(u3));
        }
    }

    float acc[2][4][4];
    #pragma unroll
    for (int m = 0; m < 2; m++)
        #pragma unroll
        for (int j = 0; j < 4; j++)
            #pragma unroll
            for (int q = 0; q < 4; q++) acc[m][j][q] = 0.f;

    constexpr int LPI = BK / 8;          // 2
    constexpr int RG  = BK / 4;          // 4
    for (int kk = 0; kk < K; kk += BK) {
        __syncthreads();
        #pragma unroll
        for (int pp = 0; pp < LPI; pp++) {
            int row = (tid / RG) + pp * (256 / RG);
            int c4 = (tid % RG) * 4;
            int gr = r0 + row;
            float4 v = make_float4(0.f, 0.f, 0.f, 0.f);
            if (gr < N) v = *(const float4*)(A + (size_t)gr * K + kk + c4);
            uint32_t u0, u1, u2, u3;
            TF32(u0, v.x); TF32(u1, v.y); TF32(u2, v.z); TF32(u3, v.w);
            AsT[c4 + 0][row] = __uint_as_float(u0);
            AsT[c4 + 1][row] = __uint_as_float(u1);
            AsT[c4 + 2][row] = __uint_as_float(u2);
            AsT[c4 + 3][row] = __uint_as_float(u3);
        }
        __syncthreads();
        #pragma unroll
        for (int kc = 0; kc < BK / 8; kc++) {
            const int kl = kc * 8;
            uint32_t bf[4][2];
            #pragma unroll
            for (int j = 0; j < 4; j++) {
                int n = warpN * 32 + j * 8 + g;
                bf[j][0] = __float_as_uint(Ws[kk + kl + tig][n]);
                bf[j][1] = __float_as_uint(Ws[kk + kl + tig + 4][n]);
            }
            #pragma unroll
            for (int m = 0; m < 2; m++) {
                int rb = warpM * 32 + m * 16;
                uint32_t a0 = __float_as_uint(AsT[kl + tig][rb + g]);
                uint32_t a1 = __float_as_uint(AsT[kl + tig][rb + g + 8]);
                uint32_t a2 = __float_as_uint(AsT[kl + tig + 4][rb + g]);
                uint32_t a3 = __float_as_uint(AsT[kl + tig + 4][rb + g + 8]);
                #pragma unroll
                for (int j = 0; j < 4; j++)
                    MMA_TF32(acc[m][j], a0, a1, a2, a3, bf[j][0], bf[j][1]);
            }
        }
    }

    const float ep = 1.0f + eps_ptr[0];
    #pragma unroll
    for (int m = 0; m < 2; m++) {
        #pragma unroll
        for (int half = 0; half < 2; half++) {
            int gr = r0 + warpM * 32 + m * 16 + g + half * 8;
            if (gr < N) {
                #pragma unroll
                for (int j = 0; j < 4; j++) {
                    int col = warpN * 32 + j * 8 + 2 * tig;
                    float v0 = acc[m][j][half * 2 + 0];
                    float v1 = acc[m][j][half * 2 + 1];
                    *(float2*)(z + (size_t)gr * HDIM + col) =
                        make_float2(v0 * ep, v1 * ep);
                    *(__half2*)(y16 + (size_t)gr * HDIM + col) =
                        __float22half2_rn(make_float2(v0, v1));
                }
            }
        }
    }
}

// ===========================================================================
// Scatter: z[dst] += w * y16[src]  (fp16 gather, fp32 vector red atomics).
// ===========================================================================
__global__ __launch_bounds__(256) void scatter_kernel(
    const int* __restrict__ src, const int* __restrict__ dst,
    const float* __restrict__ ew, const __half* __restrict__ y16,
    float* __restrict__ z, int E)
{
    __shared__ int s_src[64], s_dst[64];
    __shared__ float s_w[64];
    const int base = blockIdx.x * 64;
    const int tid = threadIdx.x;
    if (tid < 64) {
        int e = base + tid;
        if (e < E) { s_src[tid] = src[e]; s_dst[tid] = dst[e]; s_w[tid] = ew[e]; }
    }
    __syncthreads();
    #pragma unroll
    for (int it = 0; it < 4; it++) {
        int idx = it * 256 + tid;
        int e = idx >> 4;
        int c = idx & 15;
        if (base + e < E) {
            float w = s_w[e];
            uint2 hv = *(const uint2*)(y16 + (size_t)s_src[e] * HDIM + c * 4);
            float2 f0 = __half22float2(*(__half2*)&hv.x);
            float2 f1 = __half22float2(*(__half2*)&hv.y);
            float4* p = (float4*)z + (size_t)s_dst[e] * 16 + c;
            asm volatile("red.global.add.v4.f32 [%0], {%1,%2,%3,%4};"
                         :: "l"(p), "f"(w * f0.x), "f"(w * f0.y),
                            "f"(w * f1.x), "f"(w * f1.y)
                         : "memory");
        }
    }
}

// ===========================================================================
// GEMM B (tf32 MMA): h2 = relu(z + ba) @ W + bb, BN stats into stat_set.
// Mainloop cloned from gemm_a_mma. Stats epilogue: bias staged in smem,
// shuffle-reduce across the 8 lanes sharing a column, then 4 atomics/lane-group.
// ===========================================================================
__global__ __launch_bounds__(256) void gemm_b_mma_kernel(
    const float* __restrict__ Zin, const float* __restrict__ W,
    const float* __restrict__ ba, const float* __restrict__ bb,
    float* __restrict__ h2, int N, int stat_set)
{
    constexpr int K = 64, BM = 128, BK = 32;
    __shared__ __align__(16) float Ws[K][WPAD];
    __shared__ __align__(16) float AsT[BK][BM + 4];
    __shared__ float s_sum[HDIM], s_ssq[HDIM], s_bias[HDIM];

    const int tid = threadIdx.x;
    const int lane = tid & 31, wid = tid >> 5;
    const int g = lane >> 2, tig = lane & 3;
    const int warpM = wid & 3, warpN = wid >> 2;
    const int r0 = blockIdx.x * BM;

    if (tid < HDIM) {
        s_sum[tid] = 0.f; s_ssq[tid] = 0.f;
        s_bias[tid] = bb[tid];
    }

    {
        #pragma unroll
        for (int i = tid; i < K * 16; i += 256) {
            int row = i >> 4, c4 = (i & 15) * 4;
            float4 v = *(const float4*)(W + (size_t)row * HDIM + c4);
            uint32_t u0, u1, u2, u3;
            TF32(u0, v.x); TF32(u1, v.y); TF32(u2, v.z); TF32(u3, v.w);
            *(float4*)&Ws[row][c4] =
                make_float4(__uint_as_float(u0), __uint_as_float(u1),
                            __uint_as_float(u2), __uint_as_float(u3));
        }
    }

    float acc[2][4][4];
    #pragma unroll
    for (int m = 0; m < 2; m++)
        #pragma unroll
        for (int j = 0; j < 4; j++)
            #pragma unroll
            for (int q = 0; q < 4; q++) acc[m][j][q] = 0.f;

    constexpr int LPI = BK / 8;
    constexpr int RG  = BK / 4;
    for (int kk = 0; kk < K; kk += BK) {
        __syncthreads();                 // covers s_* init on first trip
        #pragma unroll
        for (int pp = 0; pp < LPI; pp++) {
            int row = (tid / RG) + pp * (256 / RG);
            int c4 = (tid % RG) * 4;
            int gr = r0 + row;
            float4 v = make_float4(0.f, 0.f, 0.f, 0.f);
            if (gr < N) {
                v = *(const float4*)(Zin + (size_t)gr * K + kk + c4);
                float4 b = *(const float4*)(ba + kk + c4);
                v.x = fmaxf(v.x + b.x, 0.f);
                v.y = fmaxf(v.y + b.y, 0.f);
                v.z = fmaxf(v.z + b.z, 0.f);
                v.w = fmaxf(v.w + b.w, 0.f);
            }
            uint32_t u0, u1, u2, u3;
            TF32(u0, v.x); TF32(u1, v.y); TF32(u2, v.z); TF32(u3, v.w);
            AsT[c4 + 0][row] = __uint_as_float(u0);
            AsT[c4 + 1][row] = __uint_as_float(u1);
            AsT[c4 + 2][row] = __uint_as_float(u2);
            AsT[c4 + 3][row] = __uint_as_float(u3);
        }
        __syncthreads();
        #pragma unroll
        for (int kc = 0; kc < BK / 8; kc++) {
            const int kl = kc * 8;
            uint32_t bf[4][2];
            #pragma unroll
            for (int j = 0; j < 4; j++) {
                int n = warpN * 32 + j * 8 + g;
                bf[j][0] = __float_as_uint(Ws[kk + kl + tig][n]);
                bf[j][1] = __float_as_uint(Ws[kk + kl + tig + 4][n]);
            }
            #pragma unroll
            for (int m = 0; m < 2; m++) {
                int rb = warpM * 32 + m * 16;
                uint32_t a0 = __float_as_uint(AsT[kl + tig][rb + g]);
                uint32_t a1 = __float_as_uint(AsT[kl + tig][rb + g + 8]);
                uint32_t a2 = __float_as_uint(AsT[kl + tig + 4][rb + g]);
                uint32_t a3 = __float_as_uint(AsT[kl + tig + 4][rb + g + 8]);
                #pragma unroll
                for (int j = 0; j < 4; j++)
                    MMA_TF32(acc[m][j], a0, a1, a2, a3, bf[j][0], bf[j][1]);
            }
        }
    }

    // Epilogue: bias + store + per-thread stat partials (fragment layout)
    float csum[4][2], cssq[4][2];
    #pragma unroll
    for (int j = 0; j < 4; j++)
        #pragma unroll
        for (int q = 0; q < 2; q++) { csum[j][q] = 0.f; cssq[j][q] = 0.f; }

    #pragma unroll
    for (int m = 0; m < 2; m++) {
        #pragma unroll
        for (int half = 0; half < 2; half++) {
            int gr = r0 + warpM * 32 + m * 16 + g + half * 8;
            if (gr < N) {
                #pragma unroll
                for (int j = 0; j < 4; j++) {
                    int col = warpN * 32 + j * 8 + 2 * tig;
                    float v0 = acc[m][j][half * 2 + 0] + s_bias[col];
                    float v1 = acc[m][j][half * 2 + 1] + s_bias[col + 1];
                    *(float2*)(h2 + (size_t)gr * HDIM + col) = make_float2(v0, v1);
                    csum[j][0] += v0; cssq[j][0] += v0 * v0;
                    csum[j][1] += v1; cssq[j][1] += v1 * v1;
                }
            }
        }
    }

    // Shuffle-reduce over the 8 lanes (same tig, varying g) sharing each column.
    const unsigned FULL = 0xFFFFFFFFu;
    #pragma unroll
    for (int j = 0; j < 4; j++) {
        #pragma unroll
        for (int q = 0; q < 2; q++) {
            float s  = csum[j][q];
            float ss = cssq[j][q];
            s  += __shfl_xor_sync(FULL, s, 4);
            s  += __shfl_xor_sync(FULL, s, 8);
            s  += __shfl_xor_sync(FULL, s, 16);
            ss += __shfl_xor_sync(FULL, ss, 4);
            ss += __shfl_xor_sync(FULL, ss, 8);
            ss += __shfl_xor_sync(FULL, ss, 16);
            if (g == 0) {
                int col = warpN * 32 + j * 8 + 2 * tig + q;
                atomicAdd(&s_sum[col], s);
                atomicAdd(&s_ssq[col], ss);
            }
        }
    }
    __syncthreads();
    if (tid < HDIM) {
        atomicAdd(&g_sum[stat_set][tid], s_sum[tid]);
        atomicAdd(&g_sumsq[stat_set][tid], s_ssq[tid]);
    }
}

// ---------------------------------------------------------------------------
// Final BN apply + residual into d_out.
// ---------------------------------------------------------------------------
__global__ __launch_bounds__(256) void bn_apply_final_kernel(
    const float* __restrict__ h2, const float* __restrict__ hprev,
    float* __restrict__ out,
    const float* __restrict__ gamma, const float* __restrict__ beta,
    int stat_set, float invN, int N)
{
    __shared__ __align__(16) float s_scale[HDIM], s_shift[HDIM];
    const int tid = threadIdx.x;
    if (tid < HDIM) {
        float mean = g_sum[stat_set][tid] * invN;
        float var  = g_sumsq[stat_set][tid] * invN - mean * mean;
        float sc   = gamma[tid] * rsqrtf(var + BN_EPS);
        s_scale[tid] = sc;
        s_shift[tid] = beta[tid] - mean * sc;
    }
    __syncthreads();
    int idx = blockIdx.x * 256 + tid;
    if (idx >= N * 16) return;
    int c4 = (idx & 15) * 4;
    float4 v = ((const float4*)h2)[idx];
    float4 sc = *(const float4*)&s_scale[c4];
    float4 sh = *(const float4*)&s_shift[c4];
    float4 p = ((const float4*)hprev)[idx];
    v.x = p.x + fmaxf(fmaf(v.x, sc.x, sh.x), 0.f);
    v.y = p.y + fmaxf(fmaf(v.y, sc.y, sh.y), 0.f);
    v.z = p.z + fmaxf(fmaf(v.z, sc.z, sh.z), 0.f);
    v.w = p.w + fmaxf(fmaf(v.w, sc.w, sh.w), 0.f);
    ((float4*)out)[idx] = v;
}

// ---------------------------------------------------------------------------
// Host launcher
// ---------------------------------------------------------------------------
extern "C" void kernel_launch(void* const* d_in, const int* in_sizes, int n_in,
                              void* d_out, int out_size)
{
    const float* x    = (const float*)d_in[0];
    const int* ei     = (const int*)d_in[1];     // int32 (JAX x64 disabled)
    const float* ew   = (const float*)d_in[2];
    const float* eps1 = (const float*)d_in[3];
    const float* W1a  = (const float*)d_in[4];
    const float* b1a  = (const float*)d_in[5];
    const float* W1b  = (const float*)d_in[6];
    const float* b1b  = (const float*)d_in[7];
    const float* g1   = (const float*)d_in[8];
    const float* be1  = (const float*)d_in[9];
    const float* epss = (const float*)d_in[10];
    const float* Wsa  = (const float*)d_in[11];
    const float* bsa  = (const float*)d_in[12];
    const float* Wsb  = (const float*)d_in[13];
    const float* bsb  = (const float*)d_in[14];
    const float* gs   = (const float*)d_in[15];
    const float* bes  = (const float*)d_in[16];

    const int F   = in_sizes[4] / in_sizes[5];   // 128
    const int N   = in_sizes[0] / F;
    const int E   = in_sizes[2];
    const int Lm1 = in_sizes[10];

    const int* src = ei;
    const int* dst = ei + E;

    __half* yb;
    float *zb, *h2b, *hb;
    cudaGetSymbolAddress((void**)&yb,  g_y16);
    cudaGetSymbolAddress((void**)&zb,  g_z);
    cudaGetSymbolAddress((void**)&h2b, g_h2);
    cudaGetSymbolAddress((void**)&hb,  g_h);

    const int gemm_blocks = (N + 127) / 128;
    const int scat_blocks = (E + 63) / 64;
    const int bn_blocks   = (N * 16 + 255) / 256;
    const float invN = 1.0f / (float)N;

    // -------- Layer 0 (K = F = 128): tf32 GEMM-first --------
    gemm_a0_mma_kernel<<<gemm_blocks, 256>>>(x, W1a, eps1, yb, zb, N);
    scatter_kernel<<<scat_blocks, 256>>>(src, dst, ew, yb, zb, E);
    gemm_b_mma_kernel<<<gemm_blocks, 256>>>(zb, W1b, b1a, b1b, h2b, N, /*set*/0);

    // -------- Hidden layers: tf32 MMA gemm_a (BN fused) + tf32 gemm_b --------
    for (int i = 0; i < Lm1; i++) {
        const float* gam = (i == 0) ? g1  : gs  + (size_t)(i - 1) * HDIM;
        const float* bet = (i == 0) ? be1 : bes + (size_t)(i - 1) * HDIM;
        gemm_a_mma_kernel<<<gemm_blocks, 256>>>(
            h2b, Wsa + (size_t)i * HDIM * HDIM, epss, i,
            gam, bet, /*stat_set=*/i, /*residual=*/(i > 0), invN,
            hb, yb, zb, N);
        scatter_kernel<<<scat_blocks, 256>>>(src, dst, ew, yb, zb, E);
        gemm_b_mma_kernel<<<gemm_blocks, 256>>>(
            zb, Wsb + (size_t)i * HDIM * HDIM,
            bsa + (size_t)i * HDIM, bsb + (size_t)i * HDIM,
            h2b, N, /*set*/i + 1);
    }

    // -------- Final BN + residual into d_out --------
    bn_apply_final_kernel<<<bn_blocks, 256>>>(
        h2b, hb, (float*)d_out,
        gs + (size_t)(Lm1 - 1) * HDIM, bes + (size_t)(Lm1 - 1) * HDIM,
        /*stat_set=*/Lm1, invN, N);
}